// round 10
// baseline (speedup 1.0000x reference)
#include <cuda_runtime.h>
#include <cuda_bf16.h>
#include <cuda_fp16.h>
#include <stdint.h>
#include <math.h>

// Problem constants
#define BQ    2
#define LQ    13294
#define SD    13294
#define MROWS (BQ * LQ)        // 26588

// Scratch (device globals: allocation-free)
__device__ __half g_val[(size_t)MROWS * 256];   // fp16 value@W_val
__device__ float  g_off[(size_t)MROWS * 256];
__device__ float  g_attn[(size_t)MROWS * 128];
__device__ float  g_acc[(size_t)MROWS * 256];

// ===========================================================================
// Helpers
// ===========================================================================
__device__ __forceinline__ uint32_t smem_u32(const void* p) {
    uint32_t a;
    asm("{ .reg .u64 t; cvta.to.shared.u64 t, %1; cvt.u32.u64 %0, t; }"
        : "=r"(a) : "l"(p));
    return a;
}

#define SW128(x) ((uint32_t)(x) ^ ((((uint32_t)(x)) >> 3) & 0x70u))

__device__ __forceinline__ uint32_t pack_bf2(__nv_bfloat16 a, __nv_bfloat16 b) {
    __nv_bfloat162 t = __halves2bfloat162(a, b);
    return *reinterpret_cast<uint32_t*>(&t);
}

__device__ __forceinline__ void ldsm_x4(uint32_t* r, uint32_t addr) {
    asm volatile("ldmatrix.sync.aligned.m8n8.x4.shared.b16 {%0,%1,%2,%3}, [%4];"
        : "=r"(r[0]), "=r"(r[1]), "=r"(r[2]), "=r"(r[3]) : "r"(addr));
}

__device__ __forceinline__ void mma16816(float* d, const uint32_t* a, const uint32_t* b) {
    asm volatile(
        "mma.sync.aligned.m16n8k16.row.col.f32.bf16.bf16.f32 "
        "{%0,%1,%2,%3}, {%4,%5,%6,%7}, {%8,%9}, {%0,%1,%2,%3};"
        : "+f"(d[0]), "+f"(d[1]), "+f"(d[2]), "+f"(d[3])
        : "r"(a[0]), "r"(a[1]), "r"(a[2]), "r"(a[3]), "r"(b[0]), "r"(b[1]));
}

// ===========================================================================
// Tensor-core GEMM via mma.sync: C[M,N] = A[M,256] @ W[256,N] + bias.
// fp32 accuracy via bf16 3-split (AhiBhi + AloBhi + AhiBlo).
// Block tile 128x128, K chunked by 64, 256 threads (8 warps = 2M x 4N).
// out_half: epilogue stores __half instead of float.
// ===========================================================================
#define SM_A_HI 0
#define SM_A_LO 16384
#define SM_B_HI 32768
#define SM_B_LO 49152
#define SM_TOTAL 65536

__global__ __launch_bounds__(256, 2)
void gemm_tc_kernel(const float* __restrict__ A, const float* __restrict__ W,
                    const float* __restrict__ bias, float* __restrict__ C,
                    int M, int N, int out_half)
{
    extern __shared__ char smem[];
    const uint32_t sb  = smem_u32(smem);
    const int tid  = threadIdx.x;
    const int wid  = tid >> 5;
    const int lane = tid & 31;
    const int bm   = blockIdx.y * 128;
    const int bn   = blockIdx.x * 128;

    const int wm = wid >> 2;
    const int wn = wid & 3;

    float acc[4][4][4];
#pragma unroll
    for (int i = 0; i < 4; ++i)
#pragma unroll
        for (int j = 0; j < 4; ++j)
#pragma unroll
            for (int r = 0; r < 4; ++r) acc[i][j][r] = 0.f;

    const int a_row_l = lane & 15;
    const int a_cb_l  = ((lane >> 4) & 1) * 16;
    const int b_row_l = ((lane >> 4) & 1) * 8 + (lane & 7);
    const int b_cb_l  = ((lane >> 3) & 1) * 16;

#pragma unroll 1
    for (int c = 0; c < 4; ++c) {
        __syncthreads();

        // ---- load + split A chunk ----
#pragma unroll
        for (int i = 0; i < 8; ++i) {
            int idx = i * 256 + tid;
            int row = idx >> 4;
            int k4  = (idx & 15) << 2;
            int gr  = bm + row;
            float4 v = make_float4(0.f, 0.f, 0.f, 0.f);
            if (gr < M) v = *(const float4*)(A + (size_t)gr * 256 + c * 64 + k4);
            __nv_bfloat16 h0 = __float2bfloat16_rn(v.x);
            __nv_bfloat16 h1 = __float2bfloat16_rn(v.y);
            __nv_bfloat16 h2 = __float2bfloat16_rn(v.z);
            __nv_bfloat16 h3 = __float2bfloat16_rn(v.w);
            __nv_bfloat16 l0 = __float2bfloat16_rn(v.x - __bfloat162float(h0));
            __nv_bfloat16 l1 = __float2bfloat16_rn(v.y - __bfloat162float(h1));
            __nv_bfloat16 l2 = __float2bfloat16_rn(v.z - __bfloat162float(h2));
            __nv_bfloat16 l3 = __float2bfloat16_rn(v.w - __bfloat162float(h3));
            uint32_t off = SW128(row * 128 + k4 * 2);
            *(uint32_t*)(smem + SM_A_HI + off)     = pack_bf2(h0, h1);
            *(uint32_t*)(smem + SM_A_HI + off + 4) = pack_bf2(h2, h3);
            *(uint32_t*)(smem + SM_A_LO + off)     = pack_bf2(l0, l1);
            *(uint32_t*)(smem + SM_A_LO + off + 4) = pack_bf2(l2, l3);
        }

        // ---- load + split + transpose B chunk: B_smem[n][k] = W[k][bn+n] ----
#pragma unroll
        for (int i = 0; i < 4; ++i) {
            int idx = i * 256 + tid;
            int kg  = idx >> 7;
            int n   = idx & 127;
            const float* wp = W + (size_t)(c * 64 + kg * 8) * N + bn + n;
            uint32_t hi[4], lo[4];
#pragma unroll
            for (int j = 0; j < 4; ++j) {
                float va = wp[(size_t)(2 * j) * N];
                float vb = wp[(size_t)(2 * j + 1) * N];
                __nv_bfloat16 ha = __float2bfloat16_rn(va);
                __nv_bfloat16 hb = __float2bfloat16_rn(vb);
                hi[j] = pack_bf2(ha, hb);
                lo[j] = pack_bf2(__float2bfloat16_rn(va - __bfloat162float(ha)),
                                 __float2bfloat16_rn(vb - __bfloat162float(hb)));
            }
            uint32_t off = SW128(n * 128 + kg * 16);
            *(uint4*)(smem + SM_B_HI + off) = make_uint4(hi[0], hi[1], hi[2], hi[3]);
            *(uint4*)(smem + SM_B_LO + off) = make_uint4(lo[0], lo[1], lo[2], lo[3]);
        }

        __syncthreads();

        // ---- tensor-core compute: 4 k-steps of 16 ----
#pragma unroll
        for (int kk = 0; kk < 4; ++kk) {
            uint32_t ah[4][4], al[4][4];
#pragma unroll
            for (int i = 0; i < 4; ++i) {
                uint32_t off = SW128((wm * 64 + i * 16 + a_row_l) * 128 +
                                     kk * 32 + a_cb_l);
                ldsm_x4(ah[i], sb + SM_A_HI + off);
                ldsm_x4(al[i], sb + SM_A_LO + off);
            }
#pragma unroll
            for (int j2 = 0; j2 < 2; ++j2) {
                uint32_t bh[4], bl[4];
                uint32_t off = SW128((wn * 32 + j2 * 16 + b_row_l) * 128 +
                                     kk * 32 + b_cb_l);
                ldsm_x4(bh, sb + SM_B_HI + off);
                ldsm_x4(bl, sb + SM_B_LO + off);
#pragma unroll
                for (int jj = 0; jj < 2; ++jj) {
                    int j = j2 * 2 + jj;
#pragma unroll
                    for (int i = 0; i < 4; ++i) {
                        mma16816(acc[i][j], ah[i], bh + jj * 2);
                        mma16816(acc[i][j], al[i], bh + jj * 2);
                        mma16816(acc[i][j], ah[i], bl + jj * 2);
                    }
                }
            }
        }
    }

    // ---- epilogue: direct global stores + bias ----
    const int tr = lane >> 2;
    const int tc = (lane & 3) * 2;
#pragma unroll
    for (int i = 0; i < 4; ++i) {
        const int row0 = bm + wm * 64 + i * 16 + tr;
        const int row1 = row0 + 8;
#pragma unroll
        for (int j = 0; j < 4; ++j) {
            const int col = bn + wn * 32 + j * 8 + tc;
            const float2 bv = *(const float2*)(bias + col);
            if (out_half) {
                __half* Ch = (__half*)C;
                if (row0 < M)
                    *(__half2*)(Ch + (size_t)row0 * N + col) =
                        __floats2half2_rn(acc[i][j][0] + bv.x, acc[i][j][1] + bv.y);
                if (row1 < M)
                    *(__half2*)(Ch + (size_t)row1 * N + col) =
                        __floats2half2_rn(acc[i][j][2] + bv.x, acc[i][j][3] + bv.y);
            } else {
                if (row0 < M) {
                    float2 o;
                    o.x = acc[i][j][0] + bv.x;
                    o.y = acc[i][j][1] + bv.y;
                    *(float2*)(C + (size_t)row0 * N + col) = o;
                }
                if (row1 < M) {
                    float2 o;
                    o.x = acc[i][j][2] + bv.x;
                    o.y = acc[i][j][3] + bv.y;
                    *(float2*)(C + (size_t)row1 * N + col) = o;
                }
            }
        }
    }
}

// ===========================================================================
// Deformable sampling: warp = (query, head). g_val is fp16 (64B gathers).
// Phase B reads s_wo two pairs at a time (float4) -> 32 LDS per warp.
// ===========================================================================
__constant__ int   c_HS[4] = {100, 50, 25, 13};
__constant__ int   c_ST[4] = {0, 10000, 12500, 13125};
__constant__ float c_HSf[4] = {100.f, 50.f, 25.f, 13.f};

__global__ __launch_bounds__(256)
void deform_sample_kernel(const float* __restrict__ refp)
{
    __shared__ __align__(16) float2 s_wo[8][64];

    const int qm   = blockIdx.x;
    const int h    = threadIdx.x >> 5;
    const int lane = threadIdx.x & 31;
    const int b    = (qm >= LQ) ? 1 : 0;

    {
        const int s = lane & 15;
        const int l = s >> 2;

        float logit = __ldg(g_attn + (size_t)qm * 128 + h * 16 + s);
        float mx = logit;
#pragma unroll
        for (int d = 8; d >= 1; d >>= 1)
            mx = fmaxf(mx, __shfl_xor_sync(0xffffffffu, mx, d));
        float e = __expf(logit - mx);
        float sum = e;
#pragma unroll
        for (int d = 8; d >= 1; d >>= 1)
            sum += __shfl_xor_sync(0xffffffffu, sum, d);
        const float lw = e / sum;

        const float2 off2 = *(const float2*)(g_off + (size_t)qm * 256 + h * 32 + s * 2);
        const float2 ref2 = *(const float2*)(refp + (size_t)qm * 8 + l * 2);

        const float Wf = c_HSf[l];
        const int   Wl = c_HS[l];
        const int   rowbase = b * SD + c_ST[l];

        const float locx = ref2.x + off2.x / Wf;
        const float locy = ref2.y + off2.y / Wf;
        const float x = locx * Wf - 0.5f;
        const float y = locy * Wf - 0.5f;

        const float x0f = floorf(x), y0f = floorf(y);
        const int   x0 = (int)x0f,  y0 = (int)y0f;
        const float wx1 = x - x0f, wx0 = 1.f - wx1;
        const float wy1 = y - y0f, wy0 = 1.f - wy1;

        const int x1 = x0 + 1, y1 = y0 + 1;
        const float mx0 = (x0 >= 0 && x0 < Wl) ? 1.f : 0.f;
        const float mx1 = (x1 >= 0 && x1 < Wl) ? 1.f : 0.f;
        const float my0 = (y0 >= 0 && y0 < Wl) ? 1.f : 0.f;
        const float my1 = (y1 >= 0 && y1 < Wl) ? 1.f : 0.f;

        const int xc0 = min(max(x0, 0), Wl - 1);
        const int xc1 = min(max(x1, 0), Wl - 1);
        const int yc0 = min(max(y0, 0), Wl - 1);
        const int yc1 = min(max(y1, 0), Wl - 1);

        const int base = rowbase * 256 + h * 32;
        if (lane < 16) {
            float2 v;
            v.x = lw * wx0 * wy0 * mx0 * my0;
            v.y = __int_as_float(base + (yc0 * Wl + xc0) * 256);
            s_wo[h][s * 4 + 0] = v;
            v.x = lw * wx1 * wy0 * mx1 * my0;
            v.y = __int_as_float(base + (yc0 * Wl + xc1) * 256);
            s_wo[h][s * 4 + 1] = v;
            v.x = lw * wx0 * wy1 * mx0 * my1;
            v.y = __int_as_float(base + (yc1 * Wl + xc0) * 256);
            s_wo[h][s * 4 + 2] = v;
            v.x = lw * wx1 * wy1 * mx1 * my1;
            v.y = __int_as_float(base + (yc1 * Wl + xc1) * 256);
            s_wo[h][s * 4 + 3] = v;
        }
    }
    __syncwarp();

    const __half* vl = g_val + lane;
    const float4* wo4 = (const float4*)s_wo[h];
    float a0 = 0.f, a1 = 0.f, a2 = 0.f, a3 = 0.f;
#pragma unroll
    for (int i = 0; i < 32; i += 2) {
        const float4 wA = wo4[i];
        const float4 wB = wo4[i + 1];
        a0 = fmaf(wA.x, __half2float(__ldg(vl + __float_as_int(wA.y))), a0);
        a1 = fmaf(wA.z, __half2float(__ldg(vl + __float_as_int(wA.w))), a1);
        a2 = fmaf(wB.x, __half2float(__ldg(vl + __float_as_int(wB.y))), a2);
        a3 = fmaf(wB.z, __half2float(__ldg(vl + __float_as_int(wB.w))), a3);
    }
    g_acc[(size_t)qm * 256 + h * 32 + lane] = (a0 + a1) + (a2 + a3);
}

// ===========================================================================
extern "C" void kernel_launch(void* const* d_in, const int* in_sizes, int n_in,
                              void* d_out, int out_size)
{
    const float* query  = (const float*)d_in[0];
    const float* refp   = (const float*)d_in[1];
    const float* value  = (const float*)d_in[2];
    const float* W_val  = (const float*)d_in[3];
    const float* b_val  = (const float*)d_in[4];
    const float* W_off  = (const float*)d_in[5];
    const float* b_off  = (const float*)d_in[6];
    const float* W_attn = (const float*)d_in[7];
    const float* b_attn = (const float*)d_in[8];
    const float* W_out  = (const float*)d_in[9];
    const float* b_out  = (const float*)d_in[10];
    float* out = (float*)d_out;

    void *gv, *go, *ga, *gc;
    cudaGetSymbolAddress(&gv, g_val);
    cudaGetSymbolAddress(&go, g_off);
    cudaGetSymbolAddress(&ga, g_attn);
    cudaGetSymbolAddress(&gc, g_acc);

    cudaFuncSetAttribute(gemm_tc_kernel,
                         cudaFuncAttributeMaxDynamicSharedMemorySize, SM_TOTAL);

    const int M = MROWS;
    const int mblocks = (M + 127) / 128;   // 208
    dim3 thr(256);

    gemm_tc_kernel<<<dim3(2, mblocks), thr, SM_TOTAL>>>(value, W_val, b_val, (float*)gv, M, 256, 1);
    gemm_tc_kernel<<<dim3(2, mblocks), thr, SM_TOTAL>>>(query, W_off, b_off, (float*)go, M, 256, 0);
    gemm_tc_kernel<<<dim3(1, mblocks), thr, SM_TOTAL>>>(query, W_attn, b_attn, (float*)ga, M, 128, 0);
    deform_sample_kernel<<<M, thr>>>(refp);
    gemm_tc_kernel<<<dim3(2, mblocks), thr, SM_TOTAL>>>((float*)gc, W_out, b_out, out, M, 256, 0);
}

// round 11
// speedup vs baseline: 1.1450x; 1.1450x over previous
#include <cuda_runtime.h>
#include <cuda_bf16.h>
#include <stdint.h>
#include <math.h>

// Problem constants
#define BQ    2
#define LQ    13294
#define SD    13294
#define MROWS (BQ * LQ)        // 26588

// Scratch (device globals: allocation-free)
__device__ float g_val[(size_t)MROWS * 256];
__device__ float g_off[(size_t)MROWS * 256];
__device__ float g_attn[(size_t)MROWS * 128];
__device__ float g_acc[(size_t)MROWS * 256];

// ===========================================================================
// Helpers
// ===========================================================================
__device__ __forceinline__ uint32_t smem_u32(const void* p) {
    uint32_t a;
    asm("{ .reg .u64 t; cvta.to.shared.u64 t, %1; cvt.u32.u64 %0, t; }"
        : "=r"(a) : "l"(p));
    return a;
}

#define SW128(x) ((uint32_t)(x) ^ ((((uint32_t)(x)) >> 3) & 0x70u))

__device__ __forceinline__ uint32_t pack_bf2(__nv_bfloat16 a, __nv_bfloat16 b) {
    __nv_bfloat162 t = __halves2bfloat162(a, b);
    return *reinterpret_cast<uint32_t*>(&t);
}

__device__ __forceinline__ void ldsm_x4(uint32_t* r, uint32_t addr) {
    asm volatile("ldmatrix.sync.aligned.m8n8.x4.shared.b16 {%0,%1,%2,%3}, [%4];"
        : "=r"(r[0]), "=r"(r[1]), "=r"(r[2]), "=r"(r[3]) : "r"(addr));
}

__device__ __forceinline__ void mma16816(float* d, const uint32_t* a, const uint32_t* b) {
    asm volatile(
        "mma.sync.aligned.m16n8k16.row.col.f32.bf16.bf16.f32 "
        "{%0,%1,%2,%3}, {%4,%5,%6,%7}, {%8,%9}, {%0,%1,%2,%3};"
        : "+f"(d[0]), "+f"(d[1]), "+f"(d[2]), "+f"(d[3])
        : "r"(a[0]), "r"(a[1]), "r"(a[2]), "r"(a[3]), "r"(b[0]), "r"(b[1]));
}

// ===========================================================================
// GEMM body (device function): 128x128 tile of C = A[M,256]@W[256,N] + bias,
// bf16 3-split (AhiBhi + AloBhi + AhiBlo) for fp32-class accuracy.
// ===========================================================================
#define SM_A_HI 0
#define SM_A_LO 16384
#define SM_B_HI 32768
#define SM_B_LO 49152
#define SM_TOTAL 65536

__device__ __forceinline__
void gemm_body(char* smem, const float* __restrict__ A, const float* __restrict__ W,
               const float* __restrict__ bias, float* __restrict__ C,
               int M, int N, int bm, int bn)
{
    const uint32_t sb  = smem_u32(smem);
    const int tid  = threadIdx.x;
    const int wid  = tid >> 5;
    const int lane = tid & 31;

    const int wm = wid >> 2;
    const int wn = wid & 3;

    float acc[4][4][4];
#pragma unroll
    for (int i = 0; i < 4; ++i)
#pragma unroll
        for (int j = 0; j < 4; ++j)
#pragma unroll
            for (int r = 0; r < 4; ++r) acc[i][j][r] = 0.f;

    const int a_row_l = lane & 15;
    const int a_cb_l  = ((lane >> 4) & 1) * 16;
    const int b_row_l = ((lane >> 4) & 1) * 8 + (lane & 7);
    const int b_cb_l  = ((lane >> 3) & 1) * 16;

#pragma unroll 1
    for (int c = 0; c < 4; ++c) {
        __syncthreads();

        // ---- load + split A chunk ----
#pragma unroll
        for (int i = 0; i < 8; ++i) {
            int idx = i * 256 + tid;
            int row = idx >> 4;
            int k4  = (idx & 15) << 2;
            int gr  = bm + row;
            float4 v = make_float4(0.f, 0.f, 0.f, 0.f);
            if (gr < M) v = *(const float4*)(A + (size_t)gr * 256 + c * 64 + k4);
            __nv_bfloat16 h0 = __float2bfloat16_rn(v.x);
            __nv_bfloat16 h1 = __float2bfloat16_rn(v.y);
            __nv_bfloat16 h2 = __float2bfloat16_rn(v.z);
            __nv_bfloat16 h3 = __float2bfloat16_rn(v.w);
            __nv_bfloat16 l0 = __float2bfloat16_rn(v.x - __bfloat162float(h0));
            __nv_bfloat16 l1 = __float2bfloat16_rn(v.y - __bfloat162float(h1));
            __nv_bfloat16 l2 = __float2bfloat16_rn(v.z - __bfloat162float(h2));
            __nv_bfloat16 l3 = __float2bfloat16_rn(v.w - __bfloat162float(h3));
            uint32_t off = SW128(row * 128 + k4 * 2);
            *(uint32_t*)(smem + SM_A_HI + off)     = pack_bf2(h0, h1);
            *(uint32_t*)(smem + SM_A_HI + off + 4) = pack_bf2(h2, h3);
            *(uint32_t*)(smem + SM_A_LO + off)     = pack_bf2(l0, l1);
            *(uint32_t*)(smem + SM_A_LO + off + 4) = pack_bf2(l2, l3);
        }

        // ---- load + split + transpose B chunk: B_smem[n][k] = W[k][bn+n] ----
#pragma unroll
        for (int i = 0; i < 4; ++i) {
            int idx = i * 256 + tid;
            int kg  = idx >> 7;
            int n   = idx & 127;
            const float* wp = W + (size_t)(c * 64 + kg * 8) * N + bn + n;
            uint32_t hi[4], lo[4];
#pragma unroll
            for (int j = 0; j < 4; ++j) {
                float va = wp[(size_t)(2 * j) * N];
                float vb = wp[(size_t)(2 * j + 1) * N];
                __nv_bfloat16 ha = __float2bfloat16_rn(va);
                __nv_bfloat16 hb = __float2bfloat16_rn(vb);
                hi[j] = pack_bf2(ha, hb);
                lo[j] = pack_bf2(__float2bfloat16_rn(va - __bfloat162float(ha)),
                                 __float2bfloat16_rn(vb - __bfloat162float(hb)));
            }
            uint32_t off = SW128(n * 128 + kg * 16);
            *(uint4*)(smem + SM_B_HI + off) = make_uint4(hi[0], hi[1], hi[2], hi[3]);
            *(uint4*)(smem + SM_B_LO + off) = make_uint4(lo[0], lo[1], lo[2], lo[3]);
        }

        __syncthreads();

        // ---- tensor-core compute: 4 k-steps of 16 ----
#pragma unroll
        for (int kk = 0; kk < 4; ++kk) {
            uint32_t ah[4][4], al[4][4];
#pragma unroll
            for (int i = 0; i < 4; ++i) {
                uint32_t off = SW128((wm * 64 + i * 16 + a_row_l) * 128 +
                                     kk * 32 + a_cb_l);
                ldsm_x4(ah[i], sb + SM_A_HI + off);
                ldsm_x4(al[i], sb + SM_A_LO + off);
            }
#pragma unroll
            for (int j2 = 0; j2 < 2; ++j2) {
                uint32_t bh[4], bl[4];
                uint32_t off = SW128((wn * 32 + j2 * 16 + b_row_l) * 128 +
                                     kk * 32 + b_cb_l);
                ldsm_x4(bh, sb + SM_B_HI + off);
                ldsm_x4(bl, sb + SM_B_LO + off);
#pragma unroll
                for (int jj = 0; jj < 2; ++jj) {
                    int j = j2 * 2 + jj;
#pragma unroll
                    for (int i = 0; i < 4; ++i) {
                        mma16816(acc[i][j], ah[i], bh + jj * 2);
                        mma16816(acc[i][j], al[i], bh + jj * 2);
                        mma16816(acc[i][j], ah[i], bl + jj * 2);
                    }
                }
            }
        }
    }

    // ---- epilogue: direct global stores + bias ----
    const int tr = lane >> 2;
    const int tc = (lane & 3) * 2;
#pragma unroll
    for (int i = 0; i < 4; ++i) {
        const int row0 = bm + wm * 64 + i * 16 + tr;
        const int row1 = row0 + 8;
#pragma unroll
        for (int j = 0; j < 4; ++j) {
            const int col = bn + wn * 32 + j * 8 + tc;
            const float2 bv = *(const float2*)(bias + col);
            if (row0 < M) {
                float2 o;
                o.x = acc[i][j][0] + bv.x;
                o.y = acc[i][j][1] + bv.y;
                *(float2*)(C + (size_t)row0 * N + col) = o;
            }
            if (row1 < M) {
                float2 o;
                o.x = acc[i][j][2] + bv.x;
                o.y = acc[i][j][3] + bv.y;
                *(float2*)(C + (size_t)row1 * N + col) = o;
            }
        }
    }
}

// Merged front GEMMs: seg 0-1 value@W_val -> g_val, seg 2-3 query@W_off -> g_off,
// seg 4 query@W_attn -> g_attn.
__global__ __launch_bounds__(256, 2)
void gemm_front_kernel(const float* __restrict__ value, const float* __restrict__ query,
                       const float* __restrict__ W_val, const float* __restrict__ b_val,
                       const float* __restrict__ W_off, const float* __restrict__ b_off,
                       const float* __restrict__ W_attn, const float* __restrict__ b_attn,
                       int M)
{
    extern __shared__ char smem[];
    const int seg = blockIdx.x;
    const int bm  = blockIdx.y * 128;
    if (seg < 2)
        gemm_body(smem, value, W_val, b_val, g_val, M, 256, bm, seg * 128);
    else if (seg < 4)
        gemm_body(smem, query, W_off, b_off, g_off, M, 256, bm, (seg - 2) * 128);
    else
        gemm_body(smem, query, W_attn, b_attn, g_attn, M, 128, bm, 0);
}

__global__ __launch_bounds__(256, 2)
void gemm_out_kernel(const float* __restrict__ W_out, const float* __restrict__ b_out,
                     float* __restrict__ out, int M)
{
    extern __shared__ char smem[];
    gemm_body(smem, g_acc, W_out, b_out, out, M, 256, blockIdx.y * 128, blockIdx.x * 128);
}

// ===========================================================================
// Deformable sampling: warp = (query, head), fp32 g_val.
// Phase B: groups of 8 corners (4 LDS.128 -> 8 LDG -> 8 FFMA), MLP=8.
// ===========================================================================
__constant__ int   c_HS[4] = {100, 50, 25, 13};
__constant__ int   c_ST[4] = {0, 10000, 12500, 13125};
__constant__ float c_HSf[4] = {100.f, 50.f, 25.f, 13.f};

__global__ __launch_bounds__(256)
void deform_sample_kernel(const float* __restrict__ refp)
{
    __shared__ __align__(16) float2 s_wo[8][64];

    const int qm   = blockIdx.x;
    const int h    = threadIdx.x >> 5;
    const int lane = threadIdx.x & 31;
    const int b    = (qm >= LQ) ? 1 : 0;

    {
        const int s = lane & 15;
        const int l = s >> 2;

        float logit = __ldg(g_attn + (size_t)qm * 128 + h * 16 + s);
        float mx = logit;
#pragma unroll
        for (int d = 8; d >= 1; d >>= 1)
            mx = fmaxf(mx, __shfl_xor_sync(0xffffffffu, mx, d));
        float e = __expf(logit - mx);
        float sum = e;
#pragma unroll
        for (int d = 8; d >= 1; d >>= 1)
            sum += __shfl_xor_sync(0xffffffffu, sum, d);
        const float lw = e / sum;

        const float2 off2 = *(const float2*)(g_off + (size_t)qm * 256 + h * 32 + s * 2);
        const float2 ref2 = *(const float2*)(refp + (size_t)qm * 8 + l * 2);

        const float Wf = c_HSf[l];
        const int   Wl = c_HS[l];
        const int   rowbase = b * SD + c_ST[l];

        const float locx = ref2.x + off2.x / Wf;
        const float locy = ref2.y + off2.y / Wf;
        const float x = locx * Wf - 0.5f;
        const float y = locy * Wf - 0.5f;

        const float x0f = floorf(x), y0f = floorf(y);
        const int   x0 = (int)x0f,  y0 = (int)y0f;
        const float wx1 = x - x0f, wx0 = 1.f - wx1;
        const float wy1 = y - y0f, wy0 = 1.f - wy1;

        const int x1 = x0 + 1, y1 = y0 + 1;
        const float mx0 = (x0 >= 0 && x0 < Wl) ? 1.f : 0.f;
        const float mx1 = (x1 >= 0 && x1 < Wl) ? 1.f : 0.f;
        const float my0 = (y0 >= 0 && y0 < Wl) ? 1.f : 0.f;
        const float my1 = (y1 >= 0 && y1 < Wl) ? 1.f : 0.f;

        const int xc0 = min(max(x0, 0), Wl - 1);
        const int xc1 = min(max(x1, 0), Wl - 1);
        const int yc0 = min(max(y0, 0), Wl - 1);
        const int yc1 = min(max(y1, 0), Wl - 1);

        const int base = rowbase * 256 + h * 32;
        if (lane < 16) {
            float2 v;
            v.x = lw * wx0 * wy0 * mx0 * my0;
            v.y = __int_as_float(base + (yc0 * Wl + xc0) * 256);
            s_wo[h][s * 4 + 0] = v;
            v.x = lw * wx1 * wy0 * mx1 * my0;
            v.y = __int_as_float(base + (yc0 * Wl + xc1) * 256);
            s_wo[h][s * 4 + 1] = v;
            v.x = lw * wx0 * wy1 * mx0 * my1;
            v.y = __int_as_float(base + (yc1 * Wl + xc0) * 256);
            s_wo[h][s * 4 + 2] = v;
            v.x = lw * wx1 * wy1 * mx1 * my1;
            v.y = __int_as_float(base + (yc1 * Wl + xc1) * 256);
            s_wo[h][s * 4 + 3] = v;
        }
    }
    __syncwarp();

    const float* vl = g_val + lane;
    const float4* wo4 = (const float4*)s_wo[h];
    float a0 = 0.f, a1 = 0.f, a2 = 0.f, a3 = 0.f;
#pragma unroll
    for (int g = 0; g < 8; ++g) {
        const float4 w0 = wo4[g * 4 + 0];
        const float4 w1 = wo4[g * 4 + 1];
        const float4 w2 = wo4[g * 4 + 2];
        const float4 w3 = wo4[g * 4 + 3];
        const float v0 = __ldg(vl + __float_as_int(w0.y));
        const float v1 = __ldg(vl + __float_as_int(w0.w));
        const float v2 = __ldg(vl + __float_as_int(w1.y));
        const float v3 = __ldg(vl + __float_as_int(w1.w));
        const float v4 = __ldg(vl + __float_as_int(w2.y));
        const float v5 = __ldg(vl + __float_as_int(w2.w));
        const float v6 = __ldg(vl + __float_as_int(w3.y));
        const float v7 = __ldg(vl + __float_as_int(w3.w));
        a0 = fmaf(w0.x, v0, a0);
        a1 = fmaf(w0.z, v1, a1);
        a2 = fmaf(w1.x, v2, a2);
        a3 = fmaf(w1.z, v3, a3);
        a0 = fmaf(w2.x, v4, a0);
        a1 = fmaf(w2.z, v5, a1);
        a2 = fmaf(w3.x, v6, a2);
        a3 = fmaf(w3.z, v7, a3);
    }
    g_acc[(size_t)qm * 256 + h * 32 + lane] = (a0 + a1) + (a2 + a3);
}

// ===========================================================================
extern "C" void kernel_launch(void* const* d_in, const int* in_sizes, int n_in,
                              void* d_out, int out_size)
{
    const float* query  = (const float*)d_in[0];
    const float* refp   = (const float*)d_in[1];
    const float* value  = (const float*)d_in[2];
    const float* W_val  = (const float*)d_in[3];
    const float* b_val  = (const float*)d_in[4];
    const float* W_off  = (const float*)d_in[5];
    const float* b_off  = (const float*)d_in[6];
    const float* W_attn = (const float*)d_in[7];
    const float* b_attn = (const float*)d_in[8];
    const float* W_out  = (const float*)d_in[9];
    const float* b_out  = (const float*)d_in[10];
    float* out = (float*)d_out;

    cudaFuncSetAttribute(gemm_front_kernel,
                         cudaFuncAttributeMaxDynamicSharedMemorySize, SM_TOTAL);
    cudaFuncSetAttribute(gemm_out_kernel,
                         cudaFuncAttributeMaxDynamicSharedMemorySize, SM_TOTAL);

    const int M = MROWS;
    const int mblocks = (M + 127) / 128;   // 208
    dim3 thr(256);

    gemm_front_kernel<<<dim3(5, mblocks), thr, SM_TOTAL>>>(
        value, query, W_val, b_val, W_off, b_off, W_attn, b_attn, M);
    deform_sample_kernel<<<M, thr>>>(refp);
    gemm_out_kernel<<<dim3(2, mblocks), thr, SM_TOTAL>>>(W_out, b_out, out, M);
}

// round 13
// speedup vs baseline: 1.1639x; 1.0165x over previous
#include <cuda_runtime.h>
#include <cuda_bf16.h>
#include <stdint.h>
#include <math.h>

// Problem constants
#define BQ    2
#define LQ    13294
#define SD    13294
#define MROWS (BQ * LQ)        // 26588

// ---------------------------------------------------------------------------
// Scratch (device globals: allocation-free)
// ---------------------------------------------------------------------------
__device__ float g_val[(size_t)MROWS * 256];     // value@W_val (fp32, gathered)
__device__ float g_off[(size_t)MROWS * 256];     // query@W_off
__device__ float g_attn[(size_t)MROWS * 128];    // query@W_attn

// pre-split bf16 operands
__device__ __nv_bfloat16 av_hi[(size_t)MROWS * 256], av_lo[(size_t)MROWS * 256]; // value
__device__ __nv_bfloat16 aq_hi[(size_t)MROWS * 256], aq_lo[(size_t)MROWS * 256]; // query
__device__ __nv_bfloat16 gacc_hi[(size_t)MROWS * 256], gacc_lo[(size_t)MROWS * 256];

// weights transposed to [N][K], split
__device__ __nv_bfloat16 wv_hi[256 * 256], wv_lo[256 * 256];
__device__ __nv_bfloat16 wo_hi[256 * 256], wo_lo[256 * 256];
__device__ __nv_bfloat16 wa_hi[128 * 256], wa_lo[128 * 256];
__device__ __nv_bfloat16 wu_hi[256 * 256], wu_lo[256 * 256];

// ---------------------------------------------------------------------------
// Helpers
// ---------------------------------------------------------------------------
__device__ __forceinline__ uint32_t smem_u32(const void* p) {
    uint32_t a;
    asm("{ .reg .u64 t; cvta.to.shared.u64 t, %1; cvt.u32.u64 %0, t; }"
        : "=r"(a) : "l"(p));
    return a;
}

#define SW64(x) ((uint32_t)(x) ^ ((((uint32_t)(x)) >> 3) & 0x30u))

__device__ __forceinline__ uint32_t pack_bf2(__nv_bfloat16 a, __nv_bfloat16 b) {
    __nv_bfloat162 t = __halves2bfloat162(a, b);
    return *reinterpret_cast<uint32_t*>(&t);
}

__device__ __forceinline__ void ldsm_x4(uint32_t* r, uint32_t addr) {
    asm volatile("ldmatrix.sync.aligned.m8n8.x4.shared.b16 {%0,%1,%2,%3}, [%4];"
        : "=r"(r[0]), "=r"(r[1]), "=r"(r[2]), "=r"(r[3]) : "r"(addr));
}

__device__ __forceinline__ void mma16816(float* d, const uint32_t* a, const uint32_t* b) {
    asm volatile(
        "mma.sync.aligned.m16n8k16.row.col.f32.bf16.bf16.f32 "
        "{%0,%1,%2,%3}, {%4,%5,%6,%7}, {%8,%9}, {%0,%1,%2,%3};"
        : "+f"(d[0]), "+f"(d[1]), "+f"(d[2]), "+f"(d[3])
        : "r"(a[0]), "r"(a[1]), "r"(a[2]), "r"(a[3]), "r"(b[0]), "r"(b[1]));
}

__device__ __forceinline__ void cp_async16(uint32_t dst, const void* src, int szfill) {
    asm volatile("cp.async.cg.shared.global [%0], [%1], 16, %2;"
                 :: "r"(dst), "l"(src), "r"(szfill) : "memory");
}
#define CP_COMMIT() asm volatile("cp.async.commit_group;" ::: "memory")
#define CP_WAIT2()  asm volatile("cp.async.wait_group 2;" ::: "memory")

__device__ __forceinline__ void split_bf16(float v, __nv_bfloat16& hi, __nv_bfloat16& lo) {
    hi = __float2bfloat16_rn(v);
    lo = __float2bfloat16_rn(v - __bfloat162float(hi));
}

// ---------------------------------------------------------------------------
// Split kernels
// ---------------------------------------------------------------------------
// W: [K=256][N] fp32 -> [N][K] bf16 hi/lo. blockIdx.y selects matrix.
__global__ __launch_bounds__(512)
void split_W_kernel(const float* __restrict__ W_val, const float* __restrict__ W_off,
                    const float* __restrict__ W_attn, const float* __restrict__ W_out)
{
    const int m = blockIdx.y;
    const float* W;
    __nv_bfloat16 *dh, *dl;
    int N;
    if (m == 0)      { W = W_val;  dh = wv_hi; dl = wv_lo; N = 256; }
    else if (m == 1) { W = W_off;  dh = wo_hi; dl = wo_lo; N = 256; }
    else if (m == 2) { W = W_attn; dh = wa_hi; dl = wa_lo; N = 128; }
    else             { W = W_out;  dh = wu_hi; dl = wu_lo; N = 256; }

    int e = blockIdx.x * 512 + threadIdx.x;
    if (e >= N * 256) return;
    int n = e >> 8, k = e & 255;
    float v = __ldg(W + (size_t)k * N + n);
    __nv_bfloat16 hi, lo;
    split_bf16(v, hi, lo);
    dh[n * 256 + k] = hi;
    dl[n * 256 + k] = lo;
}

// A: [M][256] fp32 -> bf16 hi/lo. blockIdx.y: 0=value, 1=query.
__global__ __launch_bounds__(256)
void split_A_kernel(const float* __restrict__ value, const float* __restrict__ query)
{
    const size_t n4 = (size_t)MROWS * 64;       // float4 count
    size_t idx = (size_t)blockIdx.x * 256 + threadIdx.x;
    if (idx >= n4) return;
    const float* src = blockIdx.y ? query : value;
    __nv_bfloat16* dh = blockIdx.y ? aq_hi : av_hi;
    __nv_bfloat16* dl = blockIdx.y ? aq_lo : av_lo;
    float4 v = ((const float4*)src)[idx];
    __nv_bfloat16 h0, h1, h2, h3, l0, l1, l2, l3;
    split_bf16(v.x, h0, l0); split_bf16(v.y, h1, l1);
    split_bf16(v.z, h2, l2); split_bf16(v.w, h3, l3);
    ((uint2*)dh)[idx] = make_uint2(pack_bf2(h0, h1), pack_bf2(h2, h3));
    ((uint2*)dl)[idx] = make_uint2(pack_bf2(l0, l1), pack_bf2(l2, l3));
}

// ---------------------------------------------------------------------------
// Pipelined tensor-core GEMM on pre-split bf16 operands.
// C[128x128 tile] = (Ah+Al)[M,256] @ (Bh+Bl)^T[N,256] + bias (3-split).
// K-chunk 32, 3-stage cp.async pipeline, SW64 swizzle (64B rows).
// ---------------------------------------------------------------------------
#define ST_A_HI 0
#define ST_A_LO 8192
#define ST_B_HI 16384
#define ST_B_LO 24576
#define ST_STRIDE 32768
#define SM_TOTAL  98304   // 3 stages

__device__ __forceinline__
void issue_stage(char* smem, uint32_t sb, int stage_buf,
                 const __nv_bfloat16* __restrict__ Ah, const __nv_bfloat16* __restrict__ Al,
                 const __nv_bfloat16* __restrict__ Bh, const __nv_bfloat16* __restrict__ Bl,
                 int M, int bm, int bn, int c, int tid)
{
    const uint32_t base = sb + stage_buf * ST_STRIDE;
#pragma unroll
    for (int i = 0; i < 2; ++i) {
        int idx = i * 256 + tid;          // 0..511
        int row = idx >> 2, seg = idx & 3;
        int gr  = bm + row;
        int sz  = (gr < M) ? 16 : 0;
        int grc = min(gr, M - 1);
        const __nv_bfloat16* sH = Ah + (size_t)grc * 256 + c * 32 + seg * 8;
        const __nv_bfloat16* sL = Al + (size_t)grc * 256 + c * 32 + seg * 8;
        uint32_t o = SW64(row * 64 + seg * 16);
        cp_async16(base + ST_A_HI + o, sH, sz);
        cp_async16(base + ST_A_LO + o, sL, sz);
    }
#pragma unroll
    for (int i = 0; i < 2; ++i) {
        int idx = i * 256 + tid;
        int n = idx >> 2, seg = idx & 3;
        const __nv_bfloat16* sH = Bh + (size_t)(bn + n) * 256 + c * 32 + seg * 8;
        const __nv_bfloat16* sL = Bl + (size_t)(bn + n) * 256 + c * 32 + seg * 8;
        uint32_t o = SW64(n * 64 + seg * 16);
        cp_async16(base + ST_B_HI + o, sH, 16);
        cp_async16(base + ST_B_LO + o, sL, 16);
    }
}

__device__ __forceinline__
void gemm_body(char* smem,
               const __nv_bfloat16* __restrict__ Ah, const __nv_bfloat16* __restrict__ Al,
               const __nv_bfloat16* __restrict__ Bh, const __nv_bfloat16* __restrict__ Bl,
               const float* __restrict__ bias, float* __restrict__ C,
               int M, int N, int bm, int bn)
{
    const uint32_t sb  = smem_u32(smem);
    const int tid  = threadIdx.x;
    const int wid  = tid >> 5;
    const int lane = tid & 31;
    const int wm = wid >> 2;
    const int wn = wid & 3;

    float acc[4][4][4];
#pragma unroll
    for (int i = 0; i < 4; ++i)
#pragma unroll
        for (int j = 0; j < 4; ++j)
#pragma unroll
            for (int r = 0; r < 4; ++r) acc[i][j][r] = 0.f;

    const int a_row_l = lane & 15;
    const int a_cb_l  = ((lane >> 4) & 1) * 16;
    const int b_row_l = ((lane >> 4) & 1) * 8 + (lane & 7);
    const int b_cb_l  = ((lane >> 3) & 1) * 16;

    // prologue: stages 0,1
    issue_stage(smem, sb, 0, Ah, Al, Bh, Bl, M, bm, bn, 0, tid);
    CP_COMMIT();
    issue_stage(smem, sb, 1, Ah, Al, Bh, Bl, M, bm, bn, 1, tid);
    CP_COMMIT();

#pragma unroll 1
    for (int c = 0; c < 8; ++c) {
        if (c + 2 < 8)
            issue_stage(smem, sb, (c + 2) % 3, Ah, Al, Bh, Bl, M, bm, bn, c + 2, tid);
        CP_COMMIT();
        CP_WAIT2();          // stage c complete
        __syncthreads();

        const uint32_t buf = sb + (c % 3) * ST_STRIDE;
#pragma unroll
        for (int kk = 0; kk < 2; ++kk) {
            uint32_t ah[4][4], al[4][4];
#pragma unroll
            for (int i = 0; i < 4; ++i) {
                uint32_t off = SW64((wm * 64 + i * 16 + a_row_l) * 64 + kk * 32 + a_cb_l);
                ldsm_x4(ah[i], buf + ST_A_HI + off);
                ldsm_x4(al[i], buf + ST_A_LO + off);
            }
#pragma unroll
            for (int j2 = 0; j2 < 2; ++j2) {
                uint32_t bh[4], bl[4];
                uint32_t off = SW64((wn * 32 + j2 * 16 + b_row_l) * 64 + kk * 32 + b_cb_l);
                ldsm_x4(bh, buf + ST_B_HI + off);
                ldsm_x4(bl, buf + ST_B_LO + off);
#pragma unroll
                for (int jj = 0; jj < 2; ++jj) {
                    int j = j2 * 2 + jj;
#pragma unroll
                    for (int i = 0; i < 4; ++i) {
                        mma16816(acc[i][j], ah[i], bh + jj * 2);
                        mma16816(acc[i][j], al[i], bh + jj * 2);
                        mma16816(acc[i][j], ah[i], bl + jj * 2);
                    }
                }
            }
        }
        __syncthreads();     // compute done before buffer reuse
    }

    // ---- epilogue ----
    const int tr = lane >> 2;
    const int tc = (lane & 3) * 2;
#pragma unroll
    for (int i = 0; i < 4; ++i) {
        const int row0 = bm + wm * 64 + i * 16 + tr;
        const int row1 = row0 + 8;
#pragma unroll
        for (int j = 0; j < 4; ++j) {
            const int col = bn + wn * 32 + j * 8 + tc;
            const float2 bv = *(const float2*)(bias + col);
            if (row0 < M) {
                float2 o;
                o.x = acc[i][j][0] + bv.x;
                o.y = acc[i][j][1] + bv.y;
                *(float2*)(C + (size_t)row0 * N + col) = o;
            }
            if (row1 < M) {
                float2 o;
                o.x = acc[i][j][2] + bv.x;
                o.y = acc[i][j][3] + bv.y;
                *(float2*)(C + (size_t)row1 * N + col) = o;
            }
        }
    }
}

// Merged front GEMMs.
__global__ __launch_bounds__(256, 2)
void gemm_front_kernel(const float* __restrict__ b_val, const float* __restrict__ b_off,
                       const float* __restrict__ b_attn, int M)
{
    extern __shared__ char smem[];
    const int seg = blockIdx.x;
    const int bm  = blockIdx.y * 128;
    if (seg < 2)
        gemm_body(smem, av_hi, av_lo, wv_hi, wv_lo, b_val, g_val, M, 256, bm, seg * 128);
    else if (seg < 4)
        gemm_body(smem, aq_hi, aq_lo, wo_hi, wo_lo, b_off, g_off, M, 256, bm, (seg - 2) * 128);
    else
        gemm_body(smem, aq_hi, aq_lo, wa_hi, wa_lo, b_attn, g_attn, M, 128, bm, 0);
}

__global__ __launch_bounds__(256, 2)
void gemm_out_kernel(const float* __restrict__ b_out, float* __restrict__ out, int M)
{
    extern __shared__ char smem[];
    gemm_body(smem, gacc_hi, gacc_lo, wu_hi, wu_lo, b_out, out,
              M, 256, blockIdx.y * 128, blockIdx.x * 128);
}

// ---------------------------------------------------------------------------
// Deformable sampling: warp = (query, head). Phase B groups of 16 (MLP=16).
// Writes g_acc as bf16 hi/lo directly.
// ---------------------------------------------------------------------------
__constant__ int   c_HS[4] = {100, 50, 25, 13};
__constant__ int   c_ST[4] = {0, 10000, 12500, 13125};
__constant__ float c_HSf[4] = {100.f, 50.f, 25.f, 13.f};

__global__ __launch_bounds__(256)
void deform_sample_kernel(const float* __restrict__ refp)
{
    __shared__ __align__(16) float2 s_wo[8][64];

    const int qm   = blockIdx.x;
    const int h    = threadIdx.x >> 5;
    const int lane = threadIdx.x & 31;
    const int b    = (qm >= LQ) ? 1 : 0;

    {
        const int s = lane & 15;
        const int l = s >> 2;

        float logit = __ldg(g_attn + (size_t)qm * 128 + h * 16 + s);
        float mx = logit;
#pragma unroll
        for (int d = 8; d >= 1; d >>= 1)
            mx = fmaxf(mx, __shfl_xor_sync(0xffffffffu, mx, d));
        float e = __expf(logit - mx);
        float sum = e;
#pragma unroll
        for (int d = 8; d >= 1; d >>= 1)
            sum += __shfl_xor_sync(0xffffffffu, sum, d);
        const float lw = e / sum;

        const float2 off2 = *(const float2*)(g_off + (size_t)qm * 256 + h * 32 + s * 2);
        const float2 ref2 = *(const float2*)(refp + (size_t)qm * 8 + l * 2);

        const float Wf = c_HSf[l];
        const int   Wl = c_HS[l];
        const int   rowbase = b * SD + c_ST[l];

        const float locx = ref2.x + off2.x / Wf;
        const float locy = ref2.y + off2.y / Wf;
        const float x = locx * Wf - 0.5f;
        const float y = locy * Wf - 0.5f;

        const float x0f = floorf(x), y0f = floorf(y);
        const int   x0 = (int)x0f,  y0 = (int)y0f;
        const float wx1 = x - x0f, wx0 = 1.f - wx1;
        const float wy1 = y - y0f, wy0 = 1.f - wy1;

        const int x1 = x0 + 1, y1 = y0 + 1;
        const float mx0 = (x0 >= 0 && x0 < Wl) ? 1.f : 0.f;
        const float mx1 = (x1 >= 0 && x1 < Wl) ? 1.f : 0.f;
        const float my0 = (y0 >= 0 && y0 < Wl) ? 1.f : 0.f;
        const float my1 = (y1 >= 0 && y1 < Wl) ? 1.f : 0.f;

        const int xc0 = min(max(x0, 0), Wl - 1);
        const int xc1 = min(max(x1, 0), Wl - 1);
        const int yc0 = min(max(y0, 0), Wl - 1);
        const int yc1 = min(max(y1, 0), Wl - 1);

        const int base = rowbase * 256 + h * 32;
        if (lane < 16) {
            float2 v;
            v.x = lw * wx0 * wy0 * mx0 * my0;
            v.y = __int_as_float(base + (yc0 * Wl + xc0) * 256);
            s_wo[h][s * 4 + 0] = v;
            v.x = lw * wx1 * wy0 * mx1 * my0;
            v.y = __int_as_float(base + (yc0 * Wl + xc1) * 256);
            s_wo[h][s * 4 + 1] = v;
            v.x = lw * wx0 * wy1 * mx0 * my1;
            v.y = __int_as_float(base + (yc1 * Wl + xc0) * 256);
            s_wo[h][s * 4 + 2] = v;
            v.x = lw * wx1 * wy1 * mx1 * my1;
            v.y = __int_as_float(base + (yc1 * Wl + xc1) * 256);
            s_wo[h][s * 4 + 3] = v;
        }
    }
    __syncwarp();

    const float* vl = g_val + lane;
    const float4* wo4 = (const float4*)s_wo[h];
    float a0 = 0.f, a1 = 0.f, a2 = 0.f, a3 = 0.f;
#pragma unroll
    for (int g = 0; g < 4; ++g) {
        float4 w[8];
        float  v[16];
#pragma unroll
        for (int u = 0; u < 8; ++u) w[u] = wo4[g * 8 + u];
#pragma unroll
        for (int u = 0; u < 8; ++u) {
            v[2 * u]     = __ldg(vl + __float_as_int(w[u].y));
            v[2 * u + 1] = __ldg(vl + __float_as_int(w[u].w));
        }
#pragma unroll
        for (int u = 0; u < 8; ++u) {
            float& dst0 = (u & 1) ? a1 : a0;
            float& dst1 = (u & 1) ? a3 : a2;
            dst0 = fmaf(w[u].x, v[2 * u], dst0);
            dst1 = fmaf(w[u].z, v[2 * u + 1], dst1);
        }
    }
    const float r = (a0 + a1) + (a2 + a3);
    __nv_bfloat16 hi, lo;
    split_bf16(r, hi, lo);
    gacc_hi[(size_t)qm * 256 + h * 32 + lane] = hi;
    gacc_lo[(size_t)qm * 256 + h * 32 + lane] = lo;
}

// ===========================================================================
extern "C" void kernel_launch(void* const* d_in, const int* in_sizes, int n_in,
                              void* d_out, int out_size)
{
    const float* query  = (const float*)d_in[0];
    const float* refp   = (const float*)d_in[1];
    const float* value  = (const float*)d_in[2];
    const float* W_val  = (const float*)d_in[3];
    const float* b_val  = (const float*)d_in[4];
    const float* W_off  = (const float*)d_in[5];
    const float* b_off  = (const float*)d_in[6];
    const float* W_attn = (const float*)d_in[7];
    const float* b_attn = (const float*)d_in[8];
    const float* W_out  = (const float*)d_in[9];
    const float* b_out  = (const float*)d_in[10];
    float* out = (float*)d_out;

    cudaFuncSetAttribute(gemm_front_kernel,
                         cudaFuncAttributeMaxDynamicSharedMemorySize, SM_TOTAL);
    cudaFuncSetAttribute(gemm_out_kernel,
                         cudaFuncAttributeMaxDynamicSharedMemorySize, SM_TOTAL);

    const int M = MROWS;
    const int mblocks = (M + 127) / 128;   // 208
    dim3 thr(256);

    split_W_kernel<<<dim3(128, 4), 512>>>(W_val, W_off, W_attn, W_out);
    {
        const size_t n4 = (size_t)MROWS * 64;
        split_A_kernel<<<dim3((unsigned)((n4 + 255) / 256), 2), 256>>>(value, query);
    }
    gemm_front_kernel<<<dim3(5, mblocks), thr, SM_TOTAL>>>(b_val, b_off, b_attn, M);
    deform_sample_kernel<<<M, thr>>>(refp);
    gemm_out_kernel<<<dim3(2, mblocks), thr, SM_TOTAL>>>(b_out, out, M);
}

// round 14
// speedup vs baseline: 1.3416x; 1.1527x over previous
#include <cuda_runtime.h>
#include <cuda_bf16.h>
#include <stdint.h>
#include <math.h>

// Problem constants
#define BQ    2
#define LQ    13294
#define SD    13294
#define MROWS (BQ * LQ)        // 26588

// ---------------------------------------------------------------------------
// Scratch (device globals: allocation-free)
// ---------------------------------------------------------------------------
__device__ float g_val[(size_t)MROWS * 256];     // value@W_val (fp32, gathered)
__device__ float g_off[(size_t)MROWS * 256];     // query@W_off
__device__ float g_attn[(size_t)MROWS * 128];    // query@W_attn

// pre-split bf16 operands
__device__ __nv_bfloat16 av_hi[(size_t)MROWS * 256], av_lo[(size_t)MROWS * 256]; // value
__device__ __nv_bfloat16 aq_hi[(size_t)MROWS * 256], aq_lo[(size_t)MROWS * 256]; // query
__device__ __nv_bfloat16 gacc_hi[(size_t)MROWS * 256], gacc_lo[(size_t)MROWS * 256];

// weights transposed to [N][K], split
__device__ __nv_bfloat16 wv_hi[256 * 256], wv_lo[256 * 256];
__device__ __nv_bfloat16 wo_hi[256 * 256], wo_lo[256 * 256];
__device__ __nv_bfloat16 wa_hi[128 * 256], wa_lo[128 * 256];
__device__ __nv_bfloat16 wu_hi[256 * 256], wu_lo[256 * 256];

// ---------------------------------------------------------------------------
// Helpers
// ---------------------------------------------------------------------------
__device__ __forceinline__ uint32_t smem_u32(const void* p) {
    uint32_t a;
    asm("{ .reg .u64 t; cvta.to.shared.u64 t, %1; cvt.u32.u64 %0, t; }"
        : "=r"(a) : "l"(p));
    return a;
}

#define SW64(x) ((uint32_t)(x) ^ ((((uint32_t)(x)) >> 3) & 0x30u))

__device__ __forceinline__ uint32_t pack_bf2(__nv_bfloat16 a, __nv_bfloat16 b) {
    __nv_bfloat162 t = __halves2bfloat162(a, b);
    return *reinterpret_cast<uint32_t*>(&t);
}

__device__ __forceinline__ void ldsm_x4(uint32_t* r, uint32_t addr) {
    asm volatile("ldmatrix.sync.aligned.m8n8.x4.shared.b16 {%0,%1,%2,%3}, [%4];"
        : "=r"(r[0]), "=r"(r[1]), "=r"(r[2]), "=r"(r[3]) : "r"(addr));
}

__device__ __forceinline__ void mma16816(float* d, const uint32_t* a, const uint32_t* b) {
    asm volatile(
        "mma.sync.aligned.m16n8k16.row.col.f32.bf16.bf16.f32 "
        "{%0,%1,%2,%3}, {%4,%5,%6,%7}, {%8,%9}, {%0,%1,%2,%3};"
        : "+f"(d[0]), "+f"(d[1]), "+f"(d[2]), "+f"(d[3])
        : "r"(a[0]), "r"(a[1]), "r"(a[2]), "r"(a[3]), "r"(b[0]), "r"(b[1]));
}

__device__ __forceinline__ void cp_async16(uint32_t dst, const void* src, int szfill) {
    asm volatile("cp.async.cg.shared.global [%0], [%1], 16, %2;"
                 :: "r"(dst), "l"(src), "r"(szfill) : "memory");
}
#define CP_COMMIT() asm volatile("cp.async.commit_group;" ::: "memory")
#define CP_WAIT2()  asm volatile("cp.async.wait_group 2;" ::: "memory")

__device__ __forceinline__ void split_bf16(float v, __nv_bfloat16& hi, __nv_bfloat16& lo) {
    hi = __float2bfloat16_rn(v);
    lo = __float2bfloat16_rn(v - __bfloat162float(hi));
}

// ---------------------------------------------------------------------------
// Split kernels
// ---------------------------------------------------------------------------
__global__ __launch_bounds__(512)
void split_W_kernel(const float* __restrict__ W_val, const float* __restrict__ W_off,
                    const float* __restrict__ W_attn, const float* __restrict__ W_out)
{
    const int m = blockIdx.y;
    const float* W;
    __nv_bfloat16 *dh, *dl;
    int N;
    if (m == 0)      { W = W_val;  dh = wv_hi; dl = wv_lo; N = 256; }
    else if (m == 1) { W = W_off;  dh = wo_hi; dl = wo_lo; N = 256; }
    else if (m == 2) { W = W_attn; dh = wa_hi; dl = wa_lo; N = 128; }
    else             { W = W_out;  dh = wu_hi; dl = wu_lo; N = 256; }

    int e = blockIdx.x * 512 + threadIdx.x;
    if (e >= N * 256) return;
    int n = e >> 8, k = e & 255;
    float v = __ldg(W + (size_t)k * N + n);
    __nv_bfloat16 hi, lo;
    split_bf16(v, hi, lo);
    dh[n * 256 + k] = hi;
    dl[n * 256 + k] = lo;
}

__global__ __launch_bounds__(256)
void split_A_kernel(const float* __restrict__ value, const float* __restrict__ query)
{
    const size_t n4 = (size_t)MROWS * 64;       // float4 count
    size_t idx = (size_t)blockIdx.x * 256 + threadIdx.x;
    if (idx >= n4) return;
    const float* src = blockIdx.y ? query : value;
    __nv_bfloat16* dh = blockIdx.y ? aq_hi : av_hi;
    __nv_bfloat16* dl = blockIdx.y ? aq_lo : av_lo;
    float4 v = ((const float4*)src)[idx];
    __nv_bfloat16 h0, h1, h2, h3, l0, l1, l2, l3;
    split_bf16(v.x, h0, l0); split_bf16(v.y, h1, l1);
    split_bf16(v.z, h2, l2); split_bf16(v.w, h3, l3);
    ((uint2*)dh)[idx] = make_uint2(pack_bf2(h0, h1), pack_bf2(h2, h3));
    ((uint2*)dl)[idx] = make_uint2(pack_bf2(l0, l1), pack_bf2(l2, l3));
}

// ---------------------------------------------------------------------------
// Pipelined tensor-core GEMM on pre-split bf16 operands (unchanged from R13).
// ---------------------------------------------------------------------------
#define ST_A_HI 0
#define ST_A_LO 8192
#define ST_B_HI 16384
#define ST_B_LO 24576
#define ST_STRIDE 32768
#define SM_TOTAL  98304   // 3 stages

__device__ __forceinline__
void issue_stage(char* smem, uint32_t sb, int stage_buf,
                 const __nv_bfloat16* __restrict__ Ah, const __nv_bfloat16* __restrict__ Al,
                 const __nv_bfloat16* __restrict__ Bh, const __nv_bfloat16* __restrict__ Bl,
                 int M, int bm, int bn, int c, int tid)
{
    const uint32_t base = sb + stage_buf * ST_STRIDE;
#pragma unroll
    for (int i = 0; i < 2; ++i) {
        int idx = i * 256 + tid;          // 0..511
        int row = idx >> 2, seg = idx & 3;
        int gr  = bm + row;
        int sz  = (gr < M) ? 16 : 0;
        int grc = min(gr, M - 1);
        const __nv_bfloat16* sH = Ah + (size_t)grc * 256 + c * 32 + seg * 8;
        const __nv_bfloat16* sL = Al + (size_t)grc * 256 + c * 32 + seg * 8;
        uint32_t o = SW64(row * 64 + seg * 16);
        cp_async16(base + ST_A_HI + o, sH, sz);
        cp_async16(base + ST_A_LO + o, sL, sz);
    }
#pragma unroll
    for (int i = 0; i < 2; ++i) {
        int idx = i * 256 + tid;
        int n = idx >> 2, seg = idx & 3;
        const __nv_bfloat16* sH = Bh + (size_t)(bn + n) * 256 + c * 32 + seg * 8;
        const __nv_bfloat16* sL = Bl + (size_t)(bn + n) * 256 + c * 32 + seg * 8;
        uint32_t o = SW64(n * 64 + seg * 16);
        cp_async16(base + ST_B_HI + o, sH, 16);
        cp_async16(base + ST_B_LO + o, sL, 16);
    }
}

__device__ __forceinline__
void gemm_body(char* smem,
               const __nv_bfloat16* __restrict__ Ah, const __nv_bfloat16* __restrict__ Al,
               const __nv_bfloat16* __restrict__ Bh, const __nv_bfloat16* __restrict__ Bl,
               const float* __restrict__ bias, float* __restrict__ C,
               int M, int N, int bm, int bn)
{
    const uint32_t sb  = smem_u32(smem);
    const int tid  = threadIdx.x;
    const int wid  = tid >> 5;
    const int lane = tid & 31;
    const int wm = wid >> 2;
    const int wn = wid & 3;

    float acc[4][4][4];
#pragma unroll
    for (int i = 0; i < 4; ++i)
#pragma unroll
        for (int j = 0; j < 4; ++j)
#pragma unroll
            for (int r = 0; r < 4; ++r) acc[i][j][r] = 0.f;

    const int a_row_l = lane & 15;
    const int a_cb_l  = ((lane >> 4) & 1) * 16;
    const int b_row_l = ((lane >> 4) & 1) * 8 + (lane & 7);
    const int b_cb_l  = ((lane >> 3) & 1) * 16;

    issue_stage(smem, sb, 0, Ah, Al, Bh, Bl, M, bm, bn, 0, tid);
    CP_COMMIT();
    issue_stage(smem, sb, 1, Ah, Al, Bh, Bl, M, bm, bn, 1, tid);
    CP_COMMIT();

#pragma unroll 1
    for (int c = 0; c < 8; ++c) {
        if (c + 2 < 8)
            issue_stage(smem, sb, (c + 2) % 3, Ah, Al, Bh, Bl, M, bm, bn, c + 2, tid);
        CP_COMMIT();
        CP_WAIT2();
        __syncthreads();

        const uint32_t buf = sb + (c % 3) * ST_STRIDE;
#pragma unroll
        for (int kk = 0; kk < 2; ++kk) {
            uint32_t ah[4][4], al[4][4];
#pragma unroll
            for (int i = 0; i < 4; ++i) {
                uint32_t off = SW64((wm * 64 + i * 16 + a_row_l) * 64 + kk * 32 + a_cb_l);
                ldsm_x4(ah[i], buf + ST_A_HI + off);
                ldsm_x4(al[i], buf + ST_A_LO + off);
            }
#pragma unroll
            for (int j2 = 0; j2 < 2; ++j2) {
                uint32_t bh[4], bl[4];
                uint32_t off = SW64((wn * 32 + j2 * 16 + b_row_l) * 64 + kk * 32 + b_cb_l);
                ldsm_x4(bh, buf + ST_B_HI + off);
                ldsm_x4(bl, buf + ST_B_LO + off);
#pragma unroll
                for (int jj = 0; jj < 2; ++jj) {
                    int j = j2 * 2 + jj;
#pragma unroll
                    for (int i = 0; i < 4; ++i) {
                        mma16816(acc[i][j], ah[i], bh + jj * 2);
                        mma16816(acc[i][j], al[i], bh + jj * 2);
                        mma16816(acc[i][j], ah[i], bl + jj * 2);
                    }
                }
            }
        }
        __syncthreads();
    }

    const int tr = lane >> 2;
    const int tc = (lane & 3) * 2;
#pragma unroll
    for (int i = 0; i < 4; ++i) {
        const int row0 = bm + wm * 64 + i * 16 + tr;
        const int row1 = row0 + 8;
#pragma unroll
        for (int j = 0; j < 4; ++j) {
            const int col = bn + wn * 32 + j * 8 + tc;
            const float2 bv = *(const float2*)(bias + col);
            if (row0 < M) {
                float2 o;
                o.x = acc[i][j][0] + bv.x;
                o.y = acc[i][j][1] + bv.y;
                *(float2*)(C + (size_t)row0 * N + col) = o;
            }
            if (row1 < M) {
                float2 o;
                o.x = acc[i][j][2] + bv.x;
                o.y = acc[i][j][3] + bv.y;
                *(float2*)(C + (size_t)row1 * N + col) = o;
            }
        }
    }
}

__global__ __launch_bounds__(256, 2)
void gemm_front_kernel(const float* __restrict__ b_val, const float* __restrict__ b_off,
                       const float* __restrict__ b_attn, int M)
{
    extern __shared__ char smem[];
    const int seg = blockIdx.x;
    const int bm  = blockIdx.y * 128;
    if (seg < 2)
        gemm_body(smem, av_hi, av_lo, wv_hi, wv_lo, b_val, g_val, M, 256, bm, seg * 128);
    else if (seg < 4)
        gemm_body(smem, aq_hi, aq_lo, wo_hi, wo_lo, b_off, g_off, M, 256, bm, (seg - 2) * 128);
    else
        gemm_body(smem, aq_hi, aq_lo, wa_hi, wa_lo, b_attn, g_attn, M, 128, bm, 0);
}

__global__ __launch_bounds__(256, 2)
void gemm_out_kernel(const float* __restrict__ b_out, float* __restrict__ out, int M)
{
    extern __shared__ char smem[];
    gemm_body(smem, gacc_hi, gacc_lo, wu_hi, wu_lo, b_out, out,
              M, 256, blockIdx.y * 128, blockIdx.x * 128);
}

// ---------------------------------------------------------------------------
// Deformable sampling v3: warp = (query, head).
// Phase B: vectorized gather — lane = (corner sub = lane>>3) x (channel quad
// = (lane&7)*4). Per 4-corner group: 1 broadcast LDS.64 + 1 LDG.128 + 4 FFMA.
// 16 LDG.128 per warp instead of 64 LDG.32 (same wavefront count, 1/4 the
// LSU instructions). Cross-corner reduction via shfl_xor 8/16; lanes 0-7
// write bf16 hi/lo quads to gacc.
// ---------------------------------------------------------------------------
__constant__ int   c_HS[4] = {100, 50, 25, 13};
__constant__ int   c_ST[4] = {0, 10000, 12500, 13125};
__constant__ float c_HSf[4] = {100.f, 50.f, 25.f, 13.f};

__global__ __launch_bounds__(256)
void deform_sample_kernel(const float* __restrict__ refp)
{
    __shared__ __align__(16) float2 s_wo[8][64];

    const int qm   = blockIdx.x;
    const int h    = threadIdx.x >> 5;
    const int lane = threadIdx.x & 31;
    const int b    = (qm >= LQ) ? 1 : 0;

    // ---- Phase A: per-sample scalar work (s = lane & 15, duplicated x2) ----
    {
        const int s = lane & 15;
        const int l = s >> 2;

        float logit = __ldg(g_attn + (size_t)qm * 128 + h * 16 + s);
        float mx = logit;
#pragma unroll
        for (int d = 8; d >= 1; d >>= 1)
            mx = fmaxf(mx, __shfl_xor_sync(0xffffffffu, mx, d));
        float e = __expf(logit - mx);
        float sum = e;
#pragma unroll
        for (int d = 8; d >= 1; d >>= 1)
            sum += __shfl_xor_sync(0xffffffffu, sum, d);
        const float lw = e / sum;

        const float2 off2 = *(const float2*)(g_off + (size_t)qm * 256 + h * 32 + s * 2);
        const float2 ref2 = *(const float2*)(refp + (size_t)qm * 8 + l * 2);

        const float Wf = c_HSf[l];
        const int   Wl = c_HS[l];
        const int   rowbase = b * SD + c_ST[l];

        const float locx = ref2.x + off2.x / Wf;
        const float locy = ref2.y + off2.y / Wf;
        const float x = locx * Wf - 0.5f;
        const float y = locy * Wf - 0.5f;

        const float x0f = floorf(x), y0f = floorf(y);
        const int   x0 = (int)x0f,  y0 = (int)y0f;
        const float wx1 = x - x0f, wx0 = 1.f - wx1;
        const float wy1 = y - y0f, wy0 = 1.f - wy1;

        const int x1 = x0 + 1, y1 = y0 + 1;
        const float mx0 = (x0 >= 0 && x0 < Wl) ? 1.f : 0.f;
        const float mx1 = (x1 >= 0 && x1 < Wl) ? 1.f : 0.f;
        const float my0 = (y0 >= 0 && y0 < Wl) ? 1.f : 0.f;
        const float my1 = (y1 >= 0 && y1 < Wl) ? 1.f : 0.f;

        const int xc0 = min(max(x0, 0), Wl - 1);
        const int xc1 = min(max(x1, 0), Wl - 1);
        const int yc0 = min(max(y0, 0), Wl - 1);
        const int yc1 = min(max(y1, 0), Wl - 1);

        const int base = rowbase * 256 + h * 32;
        if (lane < 16) {
            float2 v;
            v.x = lw * wx0 * wy0 * mx0 * my0;
            v.y = __int_as_float(base + (yc0 * Wl + xc0) * 256);
            s_wo[h][s * 4 + 0] = v;
            v.x = lw * wx1 * wy0 * mx1 * my0;
            v.y = __int_as_float(base + (yc0 * Wl + xc1) * 256);
            s_wo[h][s * 4 + 1] = v;
            v.x = lw * wx0 * wy1 * mx0 * my1;
            v.y = __int_as_float(base + (yc1 * Wl + xc0) * 256);
            s_wo[h][s * 4 + 2] = v;
            v.x = lw * wx1 * wy1 * mx1 * my1;
            v.y = __int_as_float(base + (yc1 * Wl + xc1) * 256);
            s_wo[h][s * 4 + 3] = v;
        }
    }
    __syncwarp();

    // ---- Phase B: vectorized gather ----
    const int sub = lane >> 3;            // corner within group of 4
    const int ch4 = (lane & 7) * 4;       // channel quad
    const float* vp = g_val + ch4;

    float ax = 0.f, ay = 0.f, az = 0.f, aw = 0.f;
#pragma unroll
    for (int g = 0; g < 16; ++g) {
        const float2 wo = s_wo[h][g * 4 + sub];
        const float4 v = __ldg((const float4*)(vp + __float_as_int(wo.y)));
        ax = fmaf(wo.x, v.x, ax);
        ay = fmaf(wo.x, v.y, ay);
        az = fmaf(wo.x, v.z, az);
        aw = fmaf(wo.x, v.w, aw);
    }

    // reduce the 4 corner-subsets (lanes +-8, +-16)
#pragma unroll
    for (int d = 8; d <= 16; d <<= 1) {
        ax += __shfl_xor_sync(0xffffffffu, ax, d);
        ay += __shfl_xor_sync(0xffffffffu, ay, d);
        az += __shfl_xor_sync(0xffffffffu, az, d);
        aw += __shfl_xor_sync(0xffffffffu, aw, d);
    }

    if (lane < 8) {
        const size_t o = (size_t)qm * 256 + h * 32 + ch4;
        __nv_bfloat16 h0, l0, h1, l1, h2, l2, h3, l3;
        split_bf16(ax, h0, l0);
        split_bf16(ay, h1, l1);
        split_bf16(az, h2, l2);
        split_bf16(aw, h3, l3);
        *(uint2*)(gacc_hi + o) = make_uint2(pack_bf2(h0, h1), pack_bf2(h2, h3));
        *(uint2*)(gacc_lo + o) = make_uint2(pack_bf2(l0, l1), pack_bf2(l2, l3));
    }
}

// ===========================================================================
extern "C" void kernel_launch(void* const* d_in, const int* in_sizes, int n_in,
                              void* d_out, int out_size)
{
    const float* query  = (const float*)d_in[0];
    const float* refp   = (const float*)d_in[1];
    const float* value  = (const float*)d_in[2];
    const float* W_val  = (const float*)d_in[3];
    const float* b_val  = (const float*)d_in[4];
    const float* W_off  = (const float*)d_in[5];
    const float* b_off  = (const float*)d_in[6];
    const float* W_attn = (const float*)d_in[7];
    const float* b_attn = (const float*)d_in[8];
    const float* W_out  = (const float*)d_in[9];
    const float* b_out  = (const float*)d_in[10];
    float* out = (float*)d_out;

    cudaFuncSetAttribute(gemm_front_kernel,
                         cudaFuncAttributeMaxDynamicSharedMemorySize, SM_TOTAL);
    cudaFuncSetAttribute(gemm_out_kernel,
                         cudaFuncAttributeMaxDynamicSharedMemorySize, SM_TOTAL);

    const int M = MROWS;
    const int mblocks = (M + 127) / 128;   // 208
    dim3 thr(256);

    split_W_kernel<<<dim3(128, 4), 512>>>(W_val, W_off, W_attn, W_out);
    {
        const size_t n4 = (size_t)MROWS * 64;
        split_A_kernel<<<dim3((unsigned)((n4 + 255) / 256), 2), 256>>>(value, query);
    }
    gemm_front_kernel<<<dim3(5, mblocks), thr, SM_TOTAL>>>(b_val, b_off, b_attn, M);
    deform_sample_kernel<<<M, thr>>>(refp);
    gemm_out_kernel<<<dim3(2, mblocks), thr, SM_TOTAL>>>(b_out, out, M);
}